// round 14
// baseline (speedup 1.0000x reference)
#include <cuda_runtime.h>
#include <math.h>
#include <stdint.h>

#define N_B   2
#define T_SEQ 2048
#define C_DIM 2048
#define NH    16
#define NKV   8
#define HD    128
#define BT    (N_B * T_SEQ)          /* 4096 */
#define QKVD  (C_DIM + 2 * NKV * HD) /* 4096 */
#define EPSV  1.1920929e-07f

/* ---- scratch (device globals: no allocations allowed) ---- */
__device__ float g_qkv[BT * QKVD];
__device__ float g_q[N_B * NH  * T_SEQ * HD];
__device__ float g_k[N_B * NKV * T_SEQ * HD];
__device__ float g_v[N_B * NKV * T_SEQ * HD];
__device__ float g_y[BT * C_DIM];

/* ============================================================
 * 3xTF32 helpers
 * ============================================================ */
__device__ __forceinline__ uint32_t f2tf32(float x) {
    uint32_t r;
    asm("cvt.rna.tf32.f32 %0, %1;" : "=r"(r) : "f"(x));
    return r;
}

__device__ __forceinline__ void split_tf32(float x, uint32_t& hi, uint32_t& lo) {
    hi = f2tf32(x);
    float r = x - __uint_as_float(hi);
    lo = f2tf32(r);
}

__device__ __forceinline__ void mma_tf32(float d[4], const uint32_t a[4],
                                         const uint32_t b[2]) {
    asm volatile(
        "mma.sync.aligned.m16n8k8.row.col.f32.tf32.tf32.f32 "
        "{%0,%1,%2,%3}, {%4,%5,%6,%7}, {%8,%9}, {%0,%1,%2,%3};"
        : "+f"(d[0]), "+f"(d[1]), "+f"(d[2]), "+f"(d[3])
        : "r"(a[0]), "r"(a[1]), "r"(a[2]), "r"(a[3]),
          "r"(b[0]), "r"(b[1]));
}

__device__ __forceinline__ void mma3_tf32(float d[4],
                                          const uint32_t ah[4], const uint32_t al[4],
                                          const uint32_t bh[2], const uint32_t bl[2]) {
    mma_tf32(d, ah, bh);
    mma_tf32(d, ah, bl);
    mma_tf32(d, al, bh);
}

/* ============================================================
 * 3xTF32 GEMM (NT) with PRE-SPLIT hi/lo smem planes.
 * CTA 128x128, 8 warps of 64x32. Each element split ONCE at the
 * store stage; mainloop is pure LDS -> MMA (no ALU splits).
 * planes: Ah/Al/Bh/Bl [2 buffers][128][KSTR] uint32 (tf32 bits)
 * ============================================================ */
#define BK   16
#define KSTR 20
#define PLANE (128 * KSTR)
#define GEMM_SMEM_BYTES (8 * PLANE * 4)   /* 81920 B */

__device__ __forceinline__ void gemm_store_slab(
    uint32_t* Ah, uint32_t* Al, uint32_t* Bh, uint32_t* Bl,
    int lrow, int lcol8, const float4 a[2], const float4 b[2])
{
    const int off = lrow * KSTR + lcol8;
    const float av[8] = {a[0].x, a[0].y, a[0].z, a[0].w,
                         a[1].x, a[1].y, a[1].z, a[1].w};
    const float bv[8] = {b[0].x, b[0].y, b[0].z, b[0].w,
                         b[1].x, b[1].y, b[1].z, b[1].w};
#pragma unroll
    for (int i = 0; i < 8; ++i) {
        uint32_t hi, lo;
        split_tf32(av[i], hi, lo);
        Ah[off + i] = hi; Al[off + i] = lo;
        split_tf32(bv[i], hi, lo);
        Bh[off + i] = hi; Bl[off + i] = lo;
    }
}

__device__ __forceinline__ void gemm_slab_mma(
    const uint32_t* Ah, const uint32_t* Al,
    const uint32_t* Bh, const uint32_t* Bl,
    int wr, int wc, int lane, float acc[4][4][4])
{
    const int r4 = lane >> 2, c4 = lane & 3;
#pragma unroll
    for (int ks = 0; ks < 2; ++ks) {
        const int k0 = ks * 8;
        uint32_t ah[4][4], al[4][4];
#pragma unroll
        for (int mi = 0; mi < 4; ++mi) {
            int rb = (wr * 64 + mi * 16 + r4) * KSTR + k0 + c4;
            int rb8 = rb + 8 * KSTR;
            ah[mi][0] = Ah[rb];      al[mi][0] = Al[rb];
            ah[mi][1] = Ah[rb8];     al[mi][1] = Al[rb8];
            ah[mi][2] = Ah[rb + 4];  al[mi][2] = Al[rb + 4];
            ah[mi][3] = Ah[rb8 + 4]; al[mi][3] = Al[rb8 + 4];
        }
#pragma unroll
        for (int ni = 0; ni < 4; ++ni) {
            int nb = (wc * 32 + ni * 8 + r4) * KSTR + k0 + c4;
            uint32_t bh[2], bl[2];
            bh[0] = Bh[nb];     bl[0] = Bl[nb];
            bh[1] = Bh[nb + 4]; bl[1] = Bl[nb + 4];
#pragma unroll
            for (int mi = 0; mi < 4; ++mi)
                mma3_tf32(acc[mi][ni], ah[mi], al[mi], bh, bl);
        }
    }
}

__global__ __launch_bounds__(256, 2)
void gemm_tf32(const float* __restrict__ A, const float* __restrict__ B,
               float* __restrict__ C, int M, int N, int K)
{
    extern __shared__ uint32_t smu[];
    uint32_t* Ah[2] = {smu,             smu + PLANE};
    uint32_t* Al[2] = {smu + 2 * PLANE, smu + 3 * PLANE};
    uint32_t* Bh[2] = {smu + 4 * PLANE, smu + 5 * PLANE};
    uint32_t* Bl[2] = {smu + 6 * PLANE, smu + 7 * PLANE};

    const int tid  = threadIdx.x;
    const int lane = tid & 31;
    const int warp = tid >> 5;
    const int wr   = warp >> 2;
    const int wc   = warp & 3;
    const int bm   = blockIdx.y * 128;
    const int bn   = blockIdx.x * 128;

    const int lrow  = tid >> 1;
    const int lcol8 = (tid & 1) * 8;

    const float* Ag = A + (size_t)(bm + lrow) * K + lcol8;
    const float* Bg = B + (size_t)(bn + lrow) * K + lcol8;

    float acc[4][4][4];
#pragma unroll
    for (int mi = 0; mi < 4; ++mi)
#pragma unroll
        for (int ni = 0; ni < 4; ++ni)
#pragma unroll
            for (int u = 0; u < 4; ++u) acc[mi][ni][u] = 0.f;

    {
        float4 a[2], b[2];
        a[0] = *(const float4*)(Ag);     a[1] = *(const float4*)(Ag + 4);
        b[0] = *(const float4*)(Bg);     b[1] = *(const float4*)(Bg + 4);
        gemm_store_slab(Ah[0], Al[0], Bh[0], Bl[0], lrow, lcol8, a, b);
    }
    __syncthreads();

    int cur = 0;
    for (int k0 = 0; k0 < K - BK; k0 += BK) {
        float4 a[2], b[2];
        a[0] = *(const float4*)(Ag + k0 + BK);
        a[1] = *(const float4*)(Ag + k0 + BK + 4);
        b[0] = *(const float4*)(Bg + k0 + BK);
        b[1] = *(const float4*)(Bg + k0 + BK + 4);

        gemm_slab_mma(Ah[cur], Al[cur], Bh[cur], Bl[cur], wr, wc, lane, acc);

        int nxt = cur ^ 1;
        gemm_store_slab(Ah[nxt], Al[nxt], Bh[nxt], Bl[nxt], lrow, lcol8, a, b);
        __syncthreads();
        cur = nxt;
    }
    gemm_slab_mma(Ah[cur], Al[cur], Bh[cur], Bl[cur], wr, wc, lane, acc);

#pragma unroll
    for (int mi = 0; mi < 4; ++mi) {
        int row = bm + wr * 64 + mi * 16 + (lane >> 2);
#pragma unroll
        for (int ni = 0; ni < 4; ++ni) {
            int col = bn + wc * 32 + ni * 8 + 2 * (lane & 3);
            *(float2*)(C + (size_t)row * N + col) =
                make_float2(acc[mi][ni][0], acc[mi][ni][1]);
            *(float2*)(C + (size_t)(row + 8) * N + col) =
                make_float2(acc[mi][ni][2], acc[mi][ni][3]);
        }
    }
}

/* ============================================================
 * RoPE + RMSNorm + head-layout scatter (unchanged)
 * ============================================================ */
__global__ __launch_bounds__(256)
void rope_kernel(const float* __restrict__ cosp, const float* __restrict__ sinp)
{
    int gw   = (blockIdx.x * blockDim.x + threadIdx.x) >> 5;
    int lane = threadIdx.x & 31;
    int j    = gw & 31;
    int bt   = gw >> 5;
    if (bt >= N_B * T_SEQ) return;
    int b = bt / T_SEQ;
    int t = bt % T_SEQ;

    const float* src;
    float* dst;
    if (j < 16) {
        src = g_qkv + (size_t)bt * QKVD + j * HD;
        dst = g_q + ((size_t)(b * NH + j) * T_SEQ + t) * HD;
    } else if (j < 24) {
        int kh = j - 16;
        src = g_qkv + (size_t)bt * QKVD + C_DIM + kh * HD;
        dst = g_k + ((size_t)(b * NKV + kh) * T_SEQ + t) * HD;
    } else {
        int kh = j - 24;
        src = g_qkv + (size_t)bt * QKVD + C_DIM + NKV * HD + kh * HD;
        dst = g_v + ((size_t)(b * NKV + kh) * T_SEQ + t) * HD;
        float4 v = ((const float4*)src)[lane];
        ((float4*)dst)[lane] = v;
        return;
    }

    float x1a = src[lane],      x1b = src[lane + 32];
    float x2a = src[lane + 64], x2b = src[lane + 96];
    float ca = cosp[t * 64 + lane], cb = cosp[t * 64 + lane + 32];
    float sa = sinp[t * 64 + lane], sb = sinp[t * 64 + lane + 32];

    float y1a =  x1a * ca + x2a * sa;
    float y2a = -x1a * sa + x2a * ca;
    float y1b =  x1b * cb + x2b * sb;
    float y2b = -x1b * sb + x2b * cb;

    float ss = y1a * y1a + y2a * y2a + y1b * y1b + y2b * y2b;
#pragma unroll
    for (int off = 16; off > 0; off >>= 1)
        ss += __shfl_xor_sync(0xffffffffu, ss, off);

    float sc = rsqrtf(ss * (1.0f / 128.0f) + EPSV);
    dst[lane]      = y1a * sc;
    dst[lane + 32] = y1b * sc;
    dst[lane + 64] = y2a * sc;
    dst[lane + 96] = y2b * sc;
}

/* ============================================================
 * Flash attention, 3xTF32 MMA (unchanged from validated round-13)
 * ============================================================ */
#define QS_STR 132
#define KS_STR 132
#define VS_STR 136
#define SS_STR 68
#define U_FLOATS (64 * VS_STR)   /* 8704 >= 64*132 */
#define ATTN_SMEM_FLOATS (64 * QS_STR + U_FLOATS + 64 * SS_STR + 192)
#define ATTN_SMEM_BYTES  (ATTN_SMEM_FLOATS * 4)

__global__ __launch_bounds__(256, 2)
void attn_kernel()
{
    extern __shared__ float sm[];
    float* Qs   = sm;                       /* [64][132] */
    float* U    = Qs + 64 * QS_STR;         /* K [64][132] then V [64][136] */
    float* Ss   = U + U_FLOATS;             /* [64][68] */
    float* rowm = Ss + 64 * SS_STR;
    float* rowl = rowm + 64;
    float* rowc = rowl + 64;

    const int tid  = threadIdx.x;
    const int lane = tid & 31;
    const int warp = tid >> 5;
    const int wm   = warp >> 1;
    const int wn   = warp & 1;
    const int r4   = lane >> 2;
    const int c4   = lane & 3;
    const int R    = wm * 16 + r4;

    const int bh = blockIdx.y;
    const int b = bh >> 4, h = bh & 15;
    const int kh = h >> 1;
    const int qt = (int)gridDim.x - 1 - (int)blockIdx.x;
    const int q0 = qt * 64;

    const float* Qg = g_q + ((size_t)(b * NH + h) * T_SEQ + q0) * HD;
    const float* Kg = g_k + ((size_t)(b * NKV + kh) * T_SEQ) * HD;
    const float* Vg = g_v + ((size_t)(b * NKV + kh) * T_SEQ) * HD;

    for (int i = tid; i < 64 * 32; i += 256) {
        int r = i >> 5, d4 = (i & 31) << 2;
        *(float4*)(Qs + r * QS_STR + d4) = *(const float4*)(Qg + r * HD + d4);
    }
    if (tid < 64) { rowm[tid] = -1e30f; rowl[tid] = 0.f; }

    float o[8][4];
#pragma unroll
    for (int ni = 0; ni < 8; ni++)
#pragma unroll
        for (int u = 0; u < 4; u++) o[ni][u] = 0.f;

    __syncthreads();
    const float scale = 0.08838834764831845f; /* 1/sqrt(128) */

    for (int kt = 0; kt <= qt; ++kt) {
        const int k0 = kt * 64;

        for (int i = tid; i < 64 * 32; i += 256) {
            int j = i >> 5, d4 = (i & 31) << 2;
            *(float4*)(U + j * KS_STR + d4) =
                *(const float4*)(Kg + (size_t)(k0 + j) * HD + d4);
        }
        __syncthreads();

        /* S = Q K^T via 3xTF32 MMA */
        {
            float s[4][4];
#pragma unroll
            for (int ni = 0; ni < 4; ni++)
#pragma unroll
                for (int u = 0; u < 4; u++) s[ni][u] = 0.f;

#pragma unroll
            for (int ks = 0; ks < 16; ++ks) {
                const int kk = ks * 8;
                uint32_t ah[4], al[4];
                split_tf32(Qs[R * QS_STR + kk + c4],           ah[0], al[0]);
                split_tf32(Qs[(R + 8) * QS_STR + kk + c4],     ah[1], al[1]);
                split_tf32(Qs[R * QS_STR + kk + c4 + 4],       ah[2], al[2]);
                split_tf32(Qs[(R + 8) * QS_STR + kk + c4 + 4], ah[3], al[3]);
#pragma unroll
                for (int ni = 0; ni < 4; ++ni) {
                    int nb = wn * 32 + ni * 8 + r4;
                    uint32_t bhh[2], bll[2];
                    split_tf32(U[nb * KS_STR + kk + c4],     bhh[0], bll[0]);
                    split_tf32(U[nb * KS_STR + kk + c4 + 4], bhh[1], bll[1]);
                    mma3_tf32(s[ni], ah, al, bhh, bll);
                }
            }
#pragma unroll
            for (int ni = 0; ni < 4; ++ni) {
                int cb = wn * 32 + ni * 8 + 2 * c4;
                *(float2*)(Ss + R * SS_STR + cb) =
                    make_float2(s[ni][0] * scale, s[ni][1] * scale);
                *(float2*)(Ss + (R + 8) * SS_STR + cb) =
                    make_float2(s[ni][2] * scale, s[ni][3] * scale);
            }
        }
        __syncthreads();

        for (int i = tid; i < 64 * 32; i += 256) {
            int j = i >> 5, d4 = (i & 31) << 2;
            *(float4*)(U + j * VS_STR + d4) =
                *(const float4*)(Vg + (size_t)(k0 + j) * HD + d4);
        }

        /* online softmax (unchanged) */
        {
            int r = tid >> 2, sub = tid & 3;
            int base = sub * 16;
            float mold = rowm[r];
            float sv[16];
            float mx = -1e30f;
            if (kt == qt) {
                int qglob = q0 + r;
#pragma unroll
                for (int c = 0; c < 16; c++) {
                    float v = Ss[r * SS_STR + base + c];
                    if (k0 + base + c > qglob) v = -1e30f;
                    sv[c] = v;
                    mx = fmaxf(mx, v);
                }
            } else {
#pragma unroll
                for (int c = 0; c < 16; c++) {
                    float v = Ss[r * SS_STR + base + c];
                    sv[c] = v;
                    mx = fmaxf(mx, v);
                }
            }
            mx = fmaxf(mx, __shfl_xor_sync(0xffffffffu, mx, 1));
            mx = fmaxf(mx, __shfl_xor_sync(0xffffffffu, mx, 2));
            float mnew = fmaxf(mold, mx);
            float psum = 0.f;
#pragma unroll
            for (int c = 0; c < 16; c++) {
                float p = __expf(sv[c] - mnew);
                Ss[r * SS_STR + base + c] = p;
                psum += p;
            }
            psum += __shfl_xor_sync(0xffffffffu, psum, 1);
            psum += __shfl_xor_sync(0xffffffffu, psum, 2);
            if (sub == 0) {
                float corr = __expf(mold - mnew);
                rowc[r] = corr;
                rowl[r] = rowl[r] * corr + psum;
                rowm[r] = mnew;
            }
        }
        __syncthreads();

        /* rescale O, then O += P V via 3xTF32 MMA */
        {
            float c0 = rowc[R], c1 = rowc[R + 8];
#pragma unroll
            for (int ni = 0; ni < 8; ni++) {
                o[ni][0] *= c0; o[ni][1] *= c0;
                o[ni][2] *= c1; o[ni][3] *= c1;
            }
#pragma unroll
            for (int ks = 0; ks < 8; ++ks) {
                const int kk = ks * 8;
                uint32_t ah[4], al[4];
                split_tf32(Ss[R * SS_STR + kk + c4],           ah[0], al[0]);
                split_tf32(Ss[(R + 8) * SS_STR + kk + c4],     ah[1], al[1]);
                split_tf32(Ss[R * SS_STR + kk + c4 + 4],       ah[2], al[2]);
                split_tf32(Ss[(R + 8) * SS_STR + kk + c4 + 4], ah[3], al[3]);
#pragma unroll
                for (int ni = 0; ni < 8; ++ni) {
                    int colb = wn * 64 + ni * 8 + r4;
                    uint32_t bhh[2], bll[2];
                    split_tf32(U[(kk + c4) * VS_STR + colb],     bhh[0], bll[0]);
                    split_tf32(U[(kk + c4 + 4) * VS_STR + colb], bhh[1], bll[1]);
                    mma3_tf32(o[ni], ah, al, bhh, bll);
                }
            }
        }
        __syncthreads();
    }

    /* epilogue */
    {
        float inv0 = 1.0f / rowl[R];
        float inv1 = 1.0f / rowl[R + 8];
        float* y0 = g_y + (size_t)b * T_SEQ * C_DIM
                  + (size_t)(q0 + R) * C_DIM + h * HD;
        float* y1 = g_y + (size_t)b * T_SEQ * C_DIM
                  + (size_t)(q0 + R + 8) * C_DIM + h * HD;
#pragma unroll
        for (int ni = 0; ni < 8; ++ni) {
            int col = wn * 64 + ni * 8 + 2 * c4;
            *(float2*)(y0 + col) = make_float2(o[ni][0] * inv0, o[ni][1] * inv0);
            *(float2*)(y1 + col) = make_float2(o[ni][2] * inv1, o[ni][3] * inv1);
        }
    }
}

/* ============================================================ */
extern "C" void kernel_launch(void* const* d_in, const int* in_sizes, int n_in,
                              void* d_out, int out_size)
{
    (void)in_sizes; (void)n_in; (void)out_size;
    const float* x      = (const float*)d_in[0];
    const float* w_attn = (const float*)d_in[1];
    const float* w_proj = (const float*)d_in[2];
    const float* cosp   = (const float*)d_in[3];
    const float* sinp   = (const float*)d_in[4];
    float* out = (float*)d_out;

    float *qkv_p, *y_p;
    cudaGetSymbolAddress((void**)&qkv_p, g_qkv);
    cudaGetSymbolAddress((void**)&y_p, g_y);

    cudaFuncSetAttribute(gemm_tf32,
                         cudaFuncAttributeMaxDynamicSharedMemorySize,
                         GEMM_SMEM_BYTES);
    cudaFuncSetAttribute(attn_kernel,
                         cudaFuncAttributeMaxDynamicSharedMemorySize,
                         ATTN_SMEM_BYTES);

    dim3 g1(QKVD / 128, BT / 128);      /* 32 x 32 */
    gemm_tf32<<<g1, 256, GEMM_SMEM_BYTES>>>(x, w_attn, qkv_p, BT, QKVD, C_DIM);

    int nwarps = N_B * T_SEQ * 32;
    rope_kernel<<<nwarps / 8, 256>>>(cosp, sinp);

    dim3 ga(T_SEQ / 64, N_B * NH);      /* 32 x 32 */
    attn_kernel<<<ga, 256, ATTN_SMEM_BYTES>>>();

    dim3 g2(C_DIM / 128, BT / 128);     /* 16 x 32 */
    gemm_tf32<<<g2, 256, GEMM_SMEM_BYTES>>>(y_p, w_proj, out, BT, C_DIM, C_DIM);
}